// round 1
// baseline (speedup 1.0000x reference)
#include <cuda_runtime.h>
#include <math.h>

// Problem constants (shapes fixed by the dataset)
#define BATCH 4
#define H 256
#define W 256
#define NIMG 8            // 4 batches x {true, pred}
#define NW 8              // 256 bits per row -> 8 u32 words
#define NPIX (BATCH*H*W)  // 262144

// ---------------- device scratch (no allocations allowed) ----------------
__device__ float    g_pp[NPIX];              // 1 MB
__device__ unsigned g_maskb[NIMG][H][NW];    // binary masks (bit-packed)
__device__ unsigned g_skelb[NIMG][H][NW];    // skeletons (bit-packed)
__device__ float    g_g2[NIMG][H][W];        // horizontal row distance squared
__device__ float    g_dist[NIMG][H][W];      // masked EDT distances
__device__ unsigned g_rmax[NIMG];            // float bits, values >= 0
__device__ unsigned g_rmin[NIMG];
__device__ double   g_sums[4];               // S1, D1, S2, D2

// ---------------- K1: elementwise + bit packing + accumulator init -------
__global__ void k_prep(const float* __restrict__ ypred,
                       const int*   __restrict__ ytrue) {
    int idx = blockIdx.x * 256 + threadIdx.x;   // exact cover of NPIX
    if (blockIdx.x == 0) {
        if (threadIdx.x < NIMG) { g_rmax[threadIdx.x] = 0u; g_rmin[threadIdx.x] = 0x7f7fffffu; }
        if (threadIdx.x < 4)    g_sums[threadIdx.x] = 0.0;
    }
    float x  = ypred[idx];
    float p  = 1.0f / (1.0f + expf(-x));
    // softmax([1-p, p]) channel 1 == sigmoid(2p - 1)
    float pp = 1.0f / (1.0f + expf(-(2.0f * p - 1.0f)));
    g_pp[idx] = pp;

    unsigned bp = __ballot_sync(0xffffffffu, x > 0.0f);     // hard = pp > 0.5
    unsigned bt = __ballot_sync(0xffffffffu, ytrue[idx] > 0);
    if ((threadIdx.x & 31) == 0) {
        int b    = idx >> 16;
        int row  = (idx >> 8) & 255;
        int word = (idx & 255) >> 5;
        g_maskb[b * 2 + 0][row][word] = bt;   // side 0 = true
        g_maskb[b * 2 + 1][row][word] = bp;   // side 1 = pred
    }
}

// ---------------- K2: fused {bitboard skeleton | horizontal EDT} ---------
// blocks [0,8): skeletonization (one block per image, one thread per row)
// blocks [8,16): horizontal 1D distance scans (one thread per row)
__global__ void k_morph() {
    if (blockIdx.x < NIMG) {
        int img = blockIdx.x;
        int t   = threadIdx.x;                 // row
        __shared__ unsigned simg[H][NW];
        __shared__ unsigned shd[H][NW];
        unsigned skel[NW];
        #pragma unroll
        for (int w = 0; w < NW; w++) { simg[t][w] = g_maskb[img][t][w]; skel[w] = 0u; }
        __syncthreads();

        // 11 iterations: delta_i = img_i & ~open(img_i); img_{i+1} = erode(img_i)
        for (int it = 0; it < 11; it++) {
            unsigned x[NW], e[NW];
            #pragma unroll
            for (int w = 0; w < NW; w++) x[w] = simg[t][w];
            unsigned vu[NW], vd[NW];
            #pragma unroll
            for (int w = 0; w < NW; w++) {
                vu[w] = (t > 0)     ? simg[t - 1][w] : 0xffffffffu;  // OOB = 1 for erosion
                vd[w] = (t < H - 1) ? simg[t + 1][w] : 0xffffffffu;
            }
            // erode = (vertical 3-AND) & (horizontal 3-AND), cross SE
            #pragma unroll
            for (int w = 0; w < NW; w++) {
                unsigned sl = (x[w] << 1) | ((w > 0)      ? (x[w - 1] >> 31) : 1u);
                unsigned sr = (x[w] >> 1) | ((w < NW - 1) ? (x[w + 1] << 31) : 0x80000000u);
                e[w] = vu[w] & vd[w] & x[w] & sl & sr;
            }
            // horizontal 3-OR of eroded row (OOB = 0 for dilation)
            #pragma unroll
            for (int w = 0; w < NW; w++) {
                unsigned ol  = (e[w] << 1) | ((w > 0)      ? (e[w - 1] >> 31) : 0u);
                unsigned orr = (e[w] >> 1) | ((w < NW - 1) ? (e[w + 1] << 31) : 0u);
                shd[t][w] = e[w] | ol | orr;
            }
            __syncthreads();
            // vertical 3-OR -> open; delta; advance img
            #pragma unroll
            for (int w = 0; w < NW; w++) {
                unsigned o = shd[t][w];
                if (t > 0)     o |= shd[t - 1][w];
                if (t < H - 1) o |= shd[t + 1][w];
                skel[w] |= x[w] & ~o;
                simg[t][w] = e[w];
            }
            __syncthreads();
        }
        #pragma unroll
        for (int w = 0; w < NW; w++) g_skelb[img][t][w] = skel[w];
    } else {
        // horizontal EDT: forward/backward scan along the row, cap at 512
        int img = blockIdx.x - NIMG;
        int row = threadIdx.x;
        unsigned bits[NW];
        #pragma unroll
        for (int w = 0; w < NW; w++) bits[w] = g_maskb[img][row][w];
        float* grow = &g_g2[img][row][0];
        float d = 512.0f;
        for (int c = 0; c < W; c++) {
            bool fg = (bits[c >> 5] >> (c & 31)) & 1u;
            d = fg ? fminf(d + 1.0f, 512.0f) : 0.0f;
            grow[c] = d;
        }
        d = 512.0f;
        for (int c = W - 1; c >= 0; c--) {
            bool fg = (bits[c >> 5] >> (c & 31)) & 1u;
            d = fg ? fminf(d + 1.0f, 512.0f) : 0.0f;
            float g = fminf(grow[c], d);
            grow[c] = g * g;
        }
    }
}

// ---------------- K3: vertical lower envelope + sqrt + rmax/rmin ---------
// One block per (image, column); exact early-exit expanding search.
__global__ void k_edt() {
    int img = blockIdx.x >> 8;
    int col = blockIdx.x & 255;
    int y   = threadIdx.x;
    __shared__ float sh[H];
    sh[y] = g_g2[img][y][col];
    __syncthreads();

    float m = sh[y];
    for (int dy = 1; dy < H; dy++) {
        float d2 = (float)(dy * dy);
        if (d2 >= m) break;                    // no farther candidate can win
        int ya = y - dy; if (ya >= 0) m = fminf(m, sh[ya] + d2);
        int yb = y + dy; if (yb < H)  m = fminf(m, sh[yb] + d2);
    }
    float dist = sqrtf(m);                     // exact-int d2 -> matches jnp.sqrt

    unsigned mb = (g_maskb[img][y][col >> 5] >> (col & 31)) & 1u;
    float dm = mb ? dist : 0.0f;               // distances = where(mask, dist, 0)
    g_dist[img][y][col] = dm;

    unsigned sb = (g_skelb[img][y][col >> 5] >> (col & 31)) & 1u;
    float sr = sb ? dm : 0.0f;                 // skel_radius

    __shared__ float rmx[H];
    __shared__ float rmn[H];
    rmx[y] = sr; rmn[y] = sr;
    __syncthreads();
    for (int s = 128; s > 0; s >>= 1) {
        if (y < s) { rmx[y] = fmaxf(rmx[y], rmx[y + s]); rmn[y] = fminf(rmn[y], rmn[y + s]); }
        __syncthreads();
    }
    if (y == 0) {  // non-negative floats: uint bit order == float order
        atomicMax(&g_rmax[img], __float_as_uint(rmx[0]));
        atomicMin(&g_rmin[img], __float_as_uint(rmn[0]));
    }
}

// ---------------- K4: fused q-maps + 4 global sums ------------------------
__global__ void k_sum() {
    int idx = blockIdx.x * 256 + threadIdx.x;
    int b   = idx >> 16;
    int row = (idx >> 8) & 255;
    int col = idx & 255;

    __shared__ float cs[4];
    if (threadIdx.x == 0) {
        cs[0] = fmaxf(__uint_as_float(g_rmax[b * 2 + 0]), 1.0f);
        cs[1] = fmaxf(__uint_as_float(g_rmin[b * 2 + 0]), 1.0f);
        cs[2] = fmaxf(__uint_as_float(g_rmax[b * 2 + 1]), 1.0f);
        cs[3] = fmaxf(__uint_as_float(g_rmin[b * 2 + 1]), 1.0f);
    }
    __syncthreads();
    float rmaxL = cs[0], rminL = cs[1], rmaxP = cs[2], rminP = cs[3];

    int w = col >> 5, s = col & 31;
    unsigned mL = (g_maskb[b * 2 + 0][row][w] >> s) & 1u;
    unsigned sL = (g_skelb[b * 2 + 0][row][w] >> s) & 1u;
    unsigned mP = (g_maskb[b * 2 + 1][row][w] >> s) & 1u;
    unsigned sP = (g_skelb[b * 2 + 1][row][w] >> s) & 1u;
    float dl = g_dist[b * 2 + 0][row][col];
    float dp = g_dist[b * 2 + 1][row][col];
    float pp = g_pp[idx];

    // true side (binary weights); skel subset of mask
    float q_vl   = mL ? fminf(dl, rmaxL) / rmaxL : 0.0f;
    float q_slvl = sL ? dl / rmaxL : 0.0f;
    float q_sl   = sL ? (rmaxL - dl + rminL) / rmaxL : 0.0f;
    // pred side (prob weights, multiplied by pp / skel_pred_prob)
    float q_vp   = mP ? (fminf(dp, rmaxP) / rmaxP) * pp : 0.0f;
    float q_spvp = sP ? (dp / rmaxP) * pp : 0.0f;
    float q_sp   = sP ? ((rmaxP - dp + rminP) / rmaxP) * pp : 0.0f;

    float t1 = q_sp * q_vl;
    float d1 = (q_spvp != 0.0f && q_slvl == 0.0f) ? q_spvp * q_sp : q_slvl * q_sp;
    float t2 = q_sl * q_vp;
    float d2 = (q_slvl != 0.0f && q_spvp == 0.0f) ? q_slvl * q_sl : q_spvp * q_sl;

    double v0 = t1, v1 = d1, v2 = t2, v3 = d2;
    #pragma unroll
    for (int off = 16; off; off >>= 1) {
        v0 += __shfl_down_sync(0xffffffffu, v0, off);
        v1 += __shfl_down_sync(0xffffffffu, v1, off);
        v2 += __shfl_down_sync(0xffffffffu, v2, off);
        v3 += __shfl_down_sync(0xffffffffu, v3, off);
    }
    __shared__ double sacc[8][4];
    int wid = threadIdx.x >> 5, lane = threadIdx.x & 31;
    if (lane == 0) { sacc[wid][0] = v0; sacc[wid][1] = v1; sacc[wid][2] = v2; sacc[wid][3] = v3; }
    __syncthreads();
    if (threadIdx.x < 4) {
        double a = 0.0;
        #pragma unroll
        for (int ww = 0; ww < 8; ww++) a += sacc[ww][threadIdx.x];
        atomicAdd(&g_sums[threadIdx.x], a);
    }
}

// ---------------- K5: scalar epilogue -------------------------------------
__global__ void k_final(float* __restrict__ out) {
    double S1 = g_sums[0], D1 = g_sums[1], S2 = g_sums[2], D2 = g_sums[3];
    double wp = (S1 + 1.0) / (D1 + 1.0);
    double ws = (S2 + 1.0) / (D2 + 1.0);
    out[0] = (float)(1.0 - 2.0 * (wp * ws) / (wp + ws));
}

// ---------------- launch ---------------------------------------------------
extern "C" void kernel_launch(void* const* d_in, const int* in_sizes, int n_in,
                              void* d_out, int out_size) {
    const float* ypred = (const float*)d_in[0];
    const int*   ytrue = (const int*)d_in[1];
    float*       out   = (float*)d_out;

    k_prep <<<NPIX / 256, 256>>>(ypred, ytrue);
    k_morph<<<2 * NIMG, 256>>>();
    k_edt  <<<NIMG * W, 256>>>();
    k_sum  <<<NPIX / 256, 256>>>();
    k_final<<<1, 1>>>(out);
}

// round 2
// speedup vs baseline: 3.2421x; 3.2421x over previous
#include <cuda_runtime.h>
#include <math.h>

#define H 256
#define W 256
#define NIMG 8            // 4 batches x {true, pred}
#define NW 8              // 256 bits per row
#define NPIX (4*H*W)      // 262144

// ---------------- device scratch ----------------
__device__ float    g_pp[NPIX];
__device__ unsigned g_maskb[NIMG][H][NW];
__device__ unsigned g_skelb[NIMG][H][NW];
__device__ float    g_dist[NIMG][H][W];
__device__ unsigned g_rmax[NIMG];            // float bits (values >= 0)
__device__ unsigned g_rmin[NIMG];
__device__ double   g_sums[4];
__device__ int      g_flag[NIMG];            // skeleton-done flags
__device__ unsigned g_count;

// ---------------- K1: elementwise + bit packing + resets ----------------
__global__ void __launch_bounds__(256) k_prep(const float* __restrict__ ypred,
                                              const int*   __restrict__ ytrue) {
    int idx = blockIdx.x * 256 + threadIdx.x;
    if (blockIdx.x == 0) {
        if (threadIdx.x < NIMG) {
            g_rmax[threadIdx.x] = 0u;
            g_rmin[threadIdx.x] = 0x7f7fffffu;
            g_flag[threadIdx.x] = 0;
        }
        if (threadIdx.x < 4) g_sums[threadIdx.x] = 0.0;
        if (threadIdx.x == 0) g_count = 0u;
    }
    float x  = ypred[idx];
    float p  = __fdividef(1.0f, 1.0f + __expf(-x));
    float pp = __fdividef(1.0f, 1.0f + __expf(1.0f - 2.0f * p)); // softmax ch1
    g_pp[idx] = pp;

    unsigned bp = __ballot_sync(0xffffffffu, x > 0.0f);          // hard = pp>0.5
    unsigned bt = __ballot_sync(0xffffffffu, ytrue[idx] > 0);
    if ((threadIdx.x & 31) == 0) {
        int b = idx >> 16, row = (idx >> 8) & 255, word = (idx & 255) >> 5;
        g_maskb[b * 2 + 0][row][word] = bt;
        g_maskb[b * 2 + 1][row][word] = bp;
    }
}

// ---------------- K2: fused skeleton | hEDT+vEDT+minmax ----------------
// blocks [0,8): bitboard skeleton, one block per image, thread = row
// blocks [8,72): EDT, one block per (image, 32-col tile)
__global__ void __launch_bounds__(256) k_mega() {
    __shared__ union Sh {
        struct { unsigned simg[H][NW]; unsigned shd[H][NW]; } sk;              // 16KB
        struct { unsigned bits[H][NW]; float shg[32][257]; unsigned skelw[H]; } ed; // ~42KB
    } S;
    __shared__ float s_red[2][8];

    int t = threadIdx.x;

    if (blockIdx.x < NIMG) {
        // ---------------- skeleton ----------------
        int img = blockIdx.x;
        unsigned skel[NW];
        #pragma unroll
        for (int w = 0; w < NW; w++) { S.sk.simg[t][w] = g_maskb[img][t][w]; skel[w] = 0u; }
        __syncthreads();

        for (int it = 0; it < 11; it++) {
            unsigned x[NW], e[NW], vu[NW], vd[NW];
            #pragma unroll
            for (int w = 0; w < NW; w++) x[w] = S.sk.simg[t][w];
            #pragma unroll
            for (int w = 0; w < NW; w++) {
                vu[w] = (t > 0)     ? S.sk.simg[t - 1][w] : 0xffffffffu;
                vd[w] = (t < H - 1) ? S.sk.simg[t + 1][w] : 0xffffffffu;
            }
            #pragma unroll
            for (int w = 0; w < NW; w++) {
                unsigned sl = (x[w] << 1) | ((w > 0)      ? (x[w - 1] >> 31) : 1u);
                unsigned sr = (x[w] >> 1) | ((w < NW - 1) ? (x[w + 1] << 31) : 0x80000000u);
                e[w] = vu[w] & vd[w] & x[w] & sl & sr;
            }
            #pragma unroll
            for (int w = 0; w < NW; w++) {
                unsigned ol  = (e[w] << 1) | ((w > 0)      ? (e[w - 1] >> 31) : 0u);
                unsigned orr = (e[w] >> 1) | ((w < NW - 1) ? (e[w + 1] << 31) : 0u);
                S.sk.shd[t][w] = e[w] | ol | orr;
            }
            __syncthreads();
            #pragma unroll
            for (int w = 0; w < NW; w++) {
                unsigned o = S.sk.shd[t][w];
                if (t > 0)     o |= S.sk.shd[t - 1][w];
                if (t < H - 1) o |= S.sk.shd[t + 1][w];
                skel[w] |= x[w] & ~o;
                S.sk.simg[t][w] = e[w];
            }
            __syncthreads();
        }
        #pragma unroll
        for (int w = 0; w < NW; w++) g_skelb[img][t][w] = skel[w];
        __threadfence();
        __syncthreads();
        if (t == 0) atomicExch(&g_flag[img], 1);   // release
        return;
    }

    // ---------------- EDT ----------------
    int b    = blockIdx.x - NIMG;
    int img  = b >> 3;
    int tile = b & 7;                 // cols [tile*32, tile*32+32)

    {   // load full image bitboard (coalesced)
        unsigned* dst = &S.ed.bits[0][0];
        const unsigned* src = &g_maskb[img][0][0];
        for (int j = t; j < H * NW; j += 256) dst[j] = src[j];
    }
    __syncthreads();

    // horizontal EDT via bit scans: thread = row t, 32 cols
    {
        unsigned zeros[NW];
        #pragma unroll
        for (int w = 0; w < NW; w++) zeros[w] = ~S.ed.bits[t][w];
        #pragma unroll 1
        for (int k = 0; k < 32; k++) {
            int c = tile * 32 + k;
            int dl = 512, dr = 512;
            unsigned v = zeros[tile] & (0xffffffffu >> (31 - k));   // bits <= k
            int ww = tile;
            while (true) {
                if (v) { dl = c - (ww * 32 + (31 - __clz(v))); break; }
                if (--ww < 0) break;
                v = zeros[ww];
            }
            v = zeros[tile] & (0xffffffffu << k);                   // bits >= k
            ww = tile;
            while (true) {
                if (v) { dr = (ww * 32 + (__ffs(v) - 1)) - c; break; }
                if (++ww >= NW) break;
                v = zeros[ww];
            }
            int g = min(min(dl, dr), 512);
            S.ed.shg[k][t] = (float)(g * g);       // conflict-free: consecutive t
        }
    }
    __syncthreads();

    // vertical lower envelope (exact early-exit expanding search)
    int c = t & 31;
    int ybase = (t >> 5) * 32;
    const float* colp = &S.ed.shg[c][0];           // padded: banks distinct per lane
    #pragma unroll 1
    for (int k = 0; k < 32; k++) {
        int y = ybase + k;
        float m = colp[y];
        for (int dy = 1; dy < H; dy++) {
            float d2 = (float)(dy * dy);
            if (d2 >= m) break;
            int ya = y - dy; if (ya >= 0) m = fminf(m, colp[ya] + d2);
            int yb = y + dy; if (yb < H)  m = fminf(m, colp[yb] + d2);
        }
        unsigned mb = (S.ed.bits[y][tile] >> c) & 1u;
        g_dist[img][y][tile * 32 + c] = mb ? sqrtf(m) : 0.0f;   // coalesced
    }

    // wait for this image's skeleton, then fold rmax/rmin atomics in
    if (t == 0) {
        while (atomicAdd(&g_flag[img], 0) == 0) { }
        __threadfence();                           // acquire
    }
    __syncthreads();
    S.ed.skelw[t] = g_skelb[img][t][tile];
    __syncthreads();

    float mx = 0.0f, mn = __int_as_float(0x7f7fffff);
    #pragma unroll 1
    for (int k = 0; k < 32; k++) {
        int y = ybase + k;
        float dm = g_dist[img][y][tile * 32 + c];  // L1-hot
        unsigned sb = (S.ed.skelw[y] >> c) & 1u;
        float sr = sb ? dm : 0.0f;                 // skel_radius (0 off-skel)
        mx = fmaxf(mx, sr);
        mn = fminf(mn, sr);
    }
    #pragma unroll
    for (int o = 16; o; o >>= 1) {
        mx = fmaxf(mx, __shfl_xor_sync(0xffffffffu, mx, o));
        mn = fminf(mn, __shfl_xor_sync(0xffffffffu, mn, o));
    }
    int wid = t >> 5;
    if ((t & 31) == 0) { s_red[0][wid] = mx; s_red[1][wid] = mn; }
    __syncthreads();
    if (t == 0) {
        float a = s_red[0][0], q = s_red[1][0];
        #pragma unroll
        for (int w = 1; w < 8; w++) { a = fmaxf(a, s_red[0][w]); q = fminf(q, s_red[1][w]); }
        atomicMax(&g_rmax[img], __float_as_uint(a));
        atomicMin(&g_rmin[img], __float_as_uint(q));
    }
}

// ---------------- K3: fused q-maps + sums + scalar epilogue ----------------
__global__ void __launch_bounds__(256) k_sum(float* __restrict__ out) {
    __shared__ float cs[4];
    __shared__ float sw[8][4];
    int t = threadIdx.x;
    int bimg = blockIdx.x >> 6;                    // 64 blocks per batch

    if (t == 0) {
        cs[0] = fmaxf(__uint_as_float(g_rmax[bimg * 2 + 0]), 1.0f);
        cs[1] = fmaxf(__uint_as_float(g_rmin[bimg * 2 + 0]), 1.0f);
        cs[2] = fmaxf(__uint_as_float(g_rmax[bimg * 2 + 1]), 1.0f);
        cs[3] = fmaxf(__uint_as_float(g_rmin[bimg * 2 + 1]), 1.0f);
    }
    __syncthreads();
    float rmaxL = cs[0], rminL = cs[1], rmaxP = cs[2], rminP = cs[3];
    float irL = 1.0f / rmaxL, irP = 1.0f / rmaxP;

    int base = (blockIdx.x * 256 + t) * 4;         // 4 consecutive pixels
    int row  = (base >> 8) & 255;
    int col  = base & 255;

    float4 dl4 = *(const float4*)&g_dist[bimg * 2 + 0][row][col];
    float4 dp4 = *(const float4*)&g_dist[bimg * 2 + 1][row][col];
    float4 pp4 = *(const float4*)&g_pp[base];
    int wsh = col & 31, wi = col >> 5;
    unsigned mLw = g_maskb[bimg * 2 + 0][row][wi] >> wsh;
    unsigned sLw = g_skelb[bimg * 2 + 0][row][wi] >> wsh;
    unsigned mPw = g_maskb[bimg * 2 + 1][row][wi] >> wsh;
    unsigned sPw = g_skelb[bimg * 2 + 1][row][wi] >> wsh;

    float dls[4] = {dl4.x, dl4.y, dl4.z, dl4.w};
    float dps[4] = {dp4.x, dp4.y, dp4.z, dp4.w};
    float pps[4] = {pp4.x, pp4.y, pp4.z, pp4.w};

    float t1 = 0.f, d1 = 0.f, t2 = 0.f, d2s = 0.f;
    #pragma unroll
    for (int j = 0; j < 4; j++) {
        bool mL = (mLw >> j) & 1, sL = (sLw >> j) & 1;
        bool mP = (mPw >> j) & 1, sP = (sPw >> j) & 1;
        float dl = dls[j], dp = dps[j], pp = pps[j];
        float q_vl   = mL ? fminf(dl, rmaxL) * irL : 0.f;
        float q_slvl = sL ? dl * irL : 0.f;
        float q_sl   = sL ? (rmaxL - dl + rminL) * irL : 0.f;
        float q_vp   = mP ? fminf(dp, rmaxP) * irP * pp : 0.f;
        float q_spvp = sP ? dp * irP * pp : 0.f;
        float q_sp   = sP ? (rmaxP - dp + rminP) * irP * pp : 0.f;
        t1  += q_sp * q_vl;
        d1  += (sP && !sL) ? q_spvp * q_sp : q_slvl * q_sp;   // combine_tensors
        t2  += q_sl * q_vp;
        d2s += (sL && !sP) ? q_slvl * q_sl : q_spvp * q_sl;
    }

    #pragma unroll
    for (int o = 16; o; o >>= 1) {
        t1  += __shfl_xor_sync(0xffffffffu, t1,  o);
        d1  += __shfl_xor_sync(0xffffffffu, d1,  o);
        t2  += __shfl_xor_sync(0xffffffffu, t2,  o);
        d2s += __shfl_xor_sync(0xffffffffu, d2s, o);
    }
    int wid = t >> 5;
    if ((t & 31) == 0) { sw[wid][0] = t1; sw[wid][1] = d1; sw[wid][2] = t2; sw[wid][3] = d2s; }
    __syncthreads();

    if (t == 0) {
        double a0 = 0.0, a1 = 0.0, a2 = 0.0, a3 = 0.0;
        #pragma unroll
        for (int w = 0; w < 8; w++) {
            a0 += (double)sw[w][0]; a1 += (double)sw[w][1];
            a2 += (double)sw[w][2]; a3 += (double)sw[w][3];
        }
        atomicAdd(&g_sums[0], a0);
        atomicAdd(&g_sums[1], a1);
        atomicAdd(&g_sums[2], a2);
        atomicAdd(&g_sums[3], a3);
        __threadfence();
        unsigned done = atomicAdd(&g_count, 1u);
        if (done == gridDim.x - 1) {               // last block: epilogue
            double S1 = atomicAdd(&g_sums[0], 0.0);
            double D1 = atomicAdd(&g_sums[1], 0.0);
            double S2 = atomicAdd(&g_sums[2], 0.0);
            double D2 = atomicAdd(&g_sums[3], 0.0);
            double wp = (S1 + 1.0) / (D1 + 1.0);
            double ws = (S2 + 1.0) / (D2 + 1.0);
            out[0] = (float)(1.0 - 2.0 * (wp * ws) / (wp + ws));
        }
    }
}

// ---------------- launch ----------------
extern "C" void kernel_launch(void* const* d_in, const int* in_sizes, int n_in,
                              void* d_out, int out_size) {
    const float* ypred = (const float*)d_in[0];
    const int*   ytrue = (const int*)d_in[1];
    float*       out   = (float*)d_out;

    k_prep<<<NPIX / 256, 256>>>(ypred, ytrue);
    k_mega<<<NIMG + NIMG * 8, 256>>>();
    k_sum <<<NPIX / 1024, 256>>>(out);
}